// round 3
// baseline (speedup 1.0000x reference)
#include <cuda_runtime.h>
#include <cuda_bf16.h>
#include <cstdint>

#define NFFT   512
#define HOPSZ  160
#define PADN   256
#define BVAL   32
#define TVAL   1024
#define FBINS  257
#define LTRIM  163680                  // (TVAL-1)*HOPSZ
#define OUTLEN 164192                  // NFFT + HOPSZ*(TVAL-1)
#define NITER  32
#define TOTF   (BVAL*TVAL*FBINS)       // 8421376
#define NFRAMES (BVAL*TVAL)            // 32768
#define PI_F 3.14159265358979323846f

// ---------------- scratch (device globals; no allocation allowed) ------------
__device__ float4 g_y4[(BVAL * OUTLEN) / 4];           // OLA buffer, 21 MB
#define G_Y ((float*)g_y4)
__device__ float2 g_ph[TOTF];                          // unit phasor, 67 MB
__device__ float  g_invwsq[OUTLEN];                    // NOLA 1/wsq (guarded)
__device__ float2 g_tw[256];                           // e^{+2πik/256} (cos,sin)
__device__ float2 g_pk[FBINS];                         // (cos(πk/256), sin(πk/256))

__device__ __forceinline__ float2 cmulf(float2 a, float2 b) {
    return make_float2(a.x * b.x - a.y * b.y, a.x * b.y + a.y * b.x);
}

// smem pad-swizzle: +1 float2 every 16 to break stride-4/stride-16 store conflicts
#define IDX(i) ((i) + ((i) >> 4))
#define SBUF 272

// ---------------------------------------------------------------------------
// 256-pt complex FFT, Stockham radix-4, 64 threads per frame (u = 0..63).
// SGN = -1 forward (e^{-i}), +1 inverse (e^{+i}, unnormalized).
// Input in A (swizzled via IDX), result ends in A. Caller writes A before call.
// ---------------------------------------------------------------------------
template <int SGN>
__device__ __forceinline__ void fft256(float2* A, float2* B, int u) {
    __syncthreads();
    float2* src = A;
    float2* dst = B;
#pragma unroll
    for (int st = 0; st < 4; st++) {
        const int Ns = 1 << (2 * st);
        const int jm = u & (Ns - 1);
        float2 v0 = src[IDX(u)];
        float2 v1 = src[IDX(u + 64)];
        float2 v2 = src[IDX(u + 128)];
        float2 v3 = src[IDX(u + 192)];
        // twiddle: e^{SGN*2πi*jm/(4Ns)} = table[jm*(64/Ns)] (conj for forward)
        float2 w1 = g_tw[jm << (6 - 2 * st)];
        if (SGN < 0) w1.y = -w1.y;
        float2 w2 = cmulf(w1, w1);
        float2 w3 = cmulf(w2, w1);
        v1 = cmulf(v1, w1);
        v2 = cmulf(v2, w2);
        v3 = cmulf(v3, w3);
        float t0x = v0.x + v2.x, t0y = v0.y + v2.y;
        float t1x = v0.x - v2.x, t1y = v0.y - v2.y;
        float t2x = v1.x + v3.x, t2y = v1.y + v3.y;
        float t3x = v1.x - v3.x, t3y = v1.y - v3.y;
        float i3x, i3y;  // SGN * i * t3
        if (SGN < 0) { i3x =  t3y; i3y = -t3x; }
        else         { i3x = -t3y; i3y =  t3x; }
        const int base = ((u >> (2 * st)) << (2 * st + 2)) + jm;  // (u/Ns)*4Ns + jm
        dst[IDX(base)]          = make_float2(t0x + t2x, t0y + t2y);
        dst[IDX(base + Ns)]     = make_float2(t1x + i3x, t1y + i3y);
        dst[IDX(base + 2 * Ns)] = make_float2(t0x - t2x, t0y - t2y);
        dst[IDX(base + 3 * Ns)] = make_float2(t1x - i3x, t1y - i3y);
        __syncthreads();
        float2* tmp = src; src = dst; dst = tmp;
    }
    // 4 stages -> result back in A
}

// ---------------------------------------------------------------------------
__global__ void k_tables() {
    int k = threadIdx.x;  // 0..256
    if (k < 256) {
        float a = (2.0f * PI_F) * (float)k / 256.0f;
        g_tw[k] = make_float2(cosf(a), sinf(a));
    }
    if (k < FBINS) {
        float b = PI_F * (float)k / 256.0f;
        g_pk[k] = make_float2(cosf(b), sinf(b));
    }
}

__global__ void k_invwsq(const float* __restrict__ win) {
    int i = blockIdx.x * blockDim.x + threadIdx.x;
    if (i >= OUTLEN) return;
    int tmax = i / HOPSZ;             if (tmax > TVAL - 1) tmax = TVAL - 1;
    int tmin = (i - (NFFT - 1) + HOPSZ - 1) / HOPSZ;  if (tmin < 0) tmin = 0;
    float s = 0.f;
    for (int t = tmin; t <= tmax; t++) {
        int n = i - t * HOPSZ;
        if (n >= 0 && n < NFFT) { float w = win[n]; s += w * w; }
    }
    g_invwsq[i] = (s > 1e-11f) ? (1.0f / s) : 1.0f;
}

__global__ void k_init_ph(const float* __restrict__ ang) {
    int i = blockIdx.x * blockDim.x + threadIdx.x;
    if (i < TOTF) {
        float s, c;
        sincosf(ang[i], &s, &c);
        g_ph[i] = make_float2(c, s);
    }
}

__global__ void k_zero_y() {
    int i = blockIdx.x * blockDim.x + threadIdx.x;
    if (i < (BVAL * OUTLEN) / 4) g_y4[i] = make_float4(0.f, 0.f, 0.f, 0.f);
}

// ---------------------------------------------------------------------------
// ISTFT: spec = mag * phasor -> irfft(512) -> * window -> atomic OLA into g_y
// 4 frames per block, 64 threads per frame.
// ---------------------------------------------------------------------------
__global__ __launch_bounds__(256) void k_istft(const float* __restrict__ mag,
                                               const float* __restrict__ win) {
    __shared__ float2 sA[4][SBUF];
    __shared__ float2 sB[4][SBUF];
    const int f = threadIdx.x >> 6;
    const int u = threadIdx.x & 63;
    const int frame = (blockIdx.x << 2) + f;
    const int b = frame >> 10;
    const int t = frame & 1023;
    const float*  magp = mag + (size_t)frame * FBINS;
    const float2* php  = g_ph + (size_t)frame * FBINS;
    float2* A  = sA[f];
    float2* Bf = sB[f];

    // Build packed Z[k] from half-spectrum X = mag*phasor (imag DC/Nyquist ignored)
#pragma unroll
    for (int q = 0; q < 4; q++) {
        int k  = u + (q << 6);       // 0..255
        int kr = 256 - k;            // 256..1
        float  mk = magp[k];
        float  mr = magp[kr];
        float2 pk = php[k];
        float2 pr = php[kr];
        float Xkx = mk * pk.x, Xky = mk * pk.y;
        float Xcx = mr * pr.x, Xcy = -mr * pr.y;   // conj(X[256-k])
        if (k == 0) { Xky = 0.f; Xcy = 0.f; }      // irfft ignores imag at DC/Nyquist
        float Zex = 0.5f * (Xkx + Xcx), Zey = 0.5f * (Xky + Xcy);
        float Bx  = 0.5f * (Xkx - Xcx), By  = 0.5f * (Xky - Xcy);
        float2 e = g_pk[k];                        // e^{+iπk/256}
        float Zox = Bx * e.x - By * e.y;
        float Zoy = Bx * e.y + By * e.x;
        A[IDX(k)] = make_float2(Zex - Zoy, Zey + Zox);   // Z = Ze + i*Zo
    }
    fft256<1>(A, Bf, u);   // inverse, unnormalized

    float* yb = G_Y + (size_t)b * OUTLEN + t * HOPSZ;
    const float2* w2p = (const float2*)win;
#pragma unroll
    for (int q = 0; q < 4; q++) {
        int m = u + (q << 6);
        float2 z = A[IDX(m)];
        float2 w = w2p[m];
        atomicAdd(yb + 2 * m,     z.x * (1.0f / 256.0f) * w.x);
        atomicAdd(yb + 2 * m + 1, z.y * (1.0f / 256.0f) * w.y);
    }
}

// ---------------------------------------------------------------------------
// STFT: gather (reflect-pad + NOLA) -> * window -> rfft(512) -> unit phasor
// ---------------------------------------------------------------------------
__device__ __forceinline__ float sample_at(const float* yb, int i) {
    int j = i - PADN;
    j = (j < 0) ? -j : j;
    if (j >= LTRIM) j = 2 * LTRIM - 2 - j;
    int idx = j + PADN;
    return yb[idx] * g_invwsq[idx];
}

__device__ __forceinline__ float2 norm_phasor(float x, float y) {
    float m2 = x * x + y * y;
    if (m2 < 1e-30f) return make_float2(1.f, 0.f);   // atan2(0,0)=0 -> (1,0)
    float inv = rsqrtf(m2);
    return make_float2(x * inv, y * inv);
}

__global__ __launch_bounds__(256) void k_stft(const float* __restrict__ win) {
    __shared__ float2 sA[4][SBUF];
    __shared__ float2 sB[4][SBUF];
    const int f = threadIdx.x >> 6;
    const int u = threadIdx.x & 63;
    const int frame = (blockIdx.x << 2) + f;
    const int b = frame >> 10;
    const int t = frame & 1023;
    const float* yb = G_Y + (size_t)b * OUTLEN;
    float2* A  = sA[f];
    float2* Bf = sB[f];
    const int i0 = t * HOPSZ;

#pragma unroll
    for (int q = 0; q < 4; q++) {
        int m  = u + (q << 6);
        int n0 = 2 * m;
        float x0 = sample_at(yb, i0 + n0);
        float x1 = sample_at(yb, i0 + n0 + 1);
        float2 w = ((const float2*)win)[m];
        A[IDX(m)] = make_float2(x0 * w.x, x1 * w.y);  // z[m] = x[2m] + i x[2m+1]
    }
    fft256<-1>(A, Bf, u);   // forward

    float2* php = g_ph + (size_t)frame * FBINS;
#pragma unroll
    for (int q = 0; q < 4; q++) {
        int k = u + (q << 6);
        float Xx, Xy;
        if (k == 0) {
            float2 Z0 = A[IDX(0)];
            Xx = Z0.x + Z0.y;   // X[0] real
            Xy = 0.f;
        } else {
            float2 Zk = A[IDX(k)];
            float2 Zr = A[IDX(256 - k)];
            float Zex = 0.5f * (Zk.x + Zr.x);
            float Zey = 0.5f * (Zk.y - Zr.y);
            float dx = Zk.x - Zr.x;
            float dy = Zk.y + Zr.y;
            float Zox = 0.5f * dy;      // Zo = -i/2 * (Zk - conj(Zr))
            float Zoy = -0.5f * dx;
            float2 e = g_pk[k];         // W^k = e^{-iπk/256} = (c, -s)
            float wx = e.x, wy = -e.y;
            Xx = Zex + Zox * wx - Zoy * wy;
            Xy = Zey + Zox * wy + Zoy * wx;
        }
        php[k] = norm_phasor(Xx, Xy);
    }
    if (u == 0) {
        float2 Z0 = A[IDX(0)];
        php[256] = norm_phasor(Z0.x - Z0.y, 0.f);   // X[256] real
    }
}

__global__ void k_out(float* __restrict__ out) {
    int i = blockIdx.x * blockDim.x + threadIdx.x;
    if (i < BVAL * LTRIM) {
        int b = i / LTRIM;
        int r = i - b * LTRIM;
        int idx = PADN + r;
        out[i] = G_Y[(size_t)b * OUTLEN + idx] * g_invwsq[idx];
    }
}

// ---------------------------------------------------------------------------
extern "C" void kernel_launch(void* const* d_in, const int* in_sizes, int n_in,
                              void* d_out, int out_size) {
    const float* mag = (const float*)d_in[0];   // [32,1024,257]
    const float* ang = (const float*)d_in[1];   // [32,1024,257]
    const float* win = (const float*)d_in[2];   // [512]
    float* out = (float*)d_out;                 // [32,163680]

    k_tables<<<1, FBINS>>>();
    k_invwsq<<<(OUTLEN + 255) / 256, 256>>>(win);
    k_init_ph<<<TOTF / 256, 256>>>(ang);

    const int zgrid = ((BVAL * OUTLEN) / 4 + 255) / 256;
    for (int it = 0; it < NITER; it++) {
        k_zero_y<<<zgrid, 256>>>();
        k_istft<<<NFRAMES / 4, 256>>>(mag, win);
        k_stft<<<NFRAMES / 4, 256>>>(win);
    }
    // final ISTFT with converged phases
    k_zero_y<<<zgrid, 256>>>();
    k_istft<<<NFRAMES / 4, 256>>>(mag, win);
    k_out<<<(BVAL * LTRIM + 255) / 256, 256>>>(out);
}

// round 4
// speedup vs baseline: 1.2155x; 1.2155x over previous
#include <cuda_runtime.h>
#include <cuda_bf16.h>
#include <cstdint>

#define NFFT   512
#define HOPSZ  160
#define PADN   256
#define BVAL   32
#define TVAL   1024
#define FBINS  257
#define LTRIM  163680                  // (TVAL-1)*HOPSZ
#define OUTLEN 164192                  // NFFT + HOPSZ*(TVAL-1)
#define NITER  32
#define TOTF   (BVAL*TVAL*FBINS)       // 8421376
#define NFRAMES (BVAL*TVAL)            // 32768
#define PI_F 3.14159265358979323846f
#define RSQ2 0.70710678118654752440f

// ---------------- scratch (device globals; no allocation allowed) ------------
__device__ float4 g_y4[(BVAL * OUTLEN) / 4];           // OLA buffer, 21 MB
#define G_Y ((float*)g_y4)
__device__ float2 g_ph[TOTF];                          // unit phasor, 67 MB
__device__ float  g_invwsq[OUTLEN];                    // NOLA 1/wsq (guarded)
__device__ float2 g_tw[256];                           // e^{+2πik/256}
__device__ float2 g_pk[FBINS];                         // (cos(πk/256), sin(πk/256))

__device__ __forceinline__ float2 cmulf(float2 a, float2 b) {
    return make_float2(a.x * b.x - a.y * b.y, a.x * b.y + a.y * b.x);
}
__device__ __forceinline__ float2 cadd(float2 a, float2 b) {
    return make_float2(a.x + b.x, a.y + b.y);
}
__device__ __forceinline__ float2 csub(float2 a, float2 b) {
    return make_float2(a.x - b.x, a.y - b.y);
}
// multiply by SGN*i
template <int SGN>
__device__ __forceinline__ float2 cmuli(float2 a) {
    return (SGN > 0) ? make_float2(-a.y, a.x) : make_float2(a.y, -a.x);
}

// padded smem index: +1 float2 every 16 (2-way .64 conflicts only == free)
#define IDXP(i) ((i) + ((i) >> 4))
#define SBUF 272

// ---------------------------------------------------------------------------
// 256-pt complex FFT, one warp per transform, 8 complex points per lane.
// Input:  v[j] = x[l + 32*j]   (natural order)
// Output: v[j] = X[j + 8*brev5(l)]   (slot j = k1, lane = bit-reversed k2)
// SGN = -1 forward (e^{-i}), +1 inverse (e^{+i}, unnormalized)
// ---------------------------------------------------------------------------
template <int SGN>
__device__ __forceinline__ void fft256_warp(float2 v[8], int l) {
    // ---- step 1: radix-8 FFT over j (stride-32 dim), DIT w/ bitrev input ----
    float2 t0 = v[0], t1 = v[4], t2 = v[2], t3 = v[6];
    float2 t4 = v[1], t5 = v[5], t6 = v[3], t7 = v[7];
    float2 a0 = cadd(t0, t1), a1 = csub(t0, t1);
    float2 a2 = cadd(t2, t3), a3 = csub(t2, t3);
    float2 a4 = cadd(t4, t5), a5 = csub(t4, t5);
    float2 a6 = cadd(t6, t7), a7 = csub(t6, t7);
    float2 i3 = cmuli<SGN>(a3), i7 = cmuli<SGN>(a7);
    float2 b0 = cadd(a0, a2), b2 = csub(a0, a2);
    float2 b1 = cadd(a1, i3), b3 = csub(a1, i3);
    float2 b4 = cadd(a4, a6), b6 = csub(a4, a6);
    float2 b5 = cadd(a5, i7), b7 = csub(a5, i7);
    // W8^1 = (c, SGN*c), W8^3 = (-c, SGN*c)
    float2 u1 = make_float2(RSQ2 * (b5.x - (float)SGN * b5.y),
                            RSQ2 * (b5.y + (float)SGN * b5.x));
    float2 u2 = cmuli<SGN>(b6);
    float2 u3 = make_float2(-RSQ2 * (b7.x + (float)SGN * b7.y),
                             RSQ2 * ((float)SGN * b7.x - b7.y));
    v[0] = cadd(b0, b4);  v[4] = csub(b0, b4);
    v[1] = cadd(b1, u1);  v[5] = csub(b1, u1);
    v[2] = cadd(b2, u2);  v[6] = csub(b2, u2);
    v[3] = cadd(b3, u3);  v[7] = csub(b3, u3);

    // ---- step 2: twiddle e^{SGN*2πi*l*k1/256} via power chain ----
    float2 w1 = g_tw[l];
    if (SGN < 0) w1.y = -w1.y;
    float2 w = w1;
    v[1] = cmulf(v[1], w);
#pragma unroll
    for (int k1 = 2; k1 < 8; k1++) {
        w = cmulf(w, w1);
        v[k1] = cmulf(v[k1], w);
    }

    // ---- step 3: 32-pt DIF FFT across lanes (5 radix-2 shfl stages) ----
#pragma unroll
    for (int s = 0; s < 5; s++) {
        const int m = 16 >> s;
        const bool hi = (l & m) != 0;
        int tidx = (l & (m - 1)) << s;          // 0..15
        float2 tw = g_tw[tidx << 3];            // e^{+2πi*tidx/32}
        if (SGN < 0) tw.y = -tw.y;
        if (!hi) tw = make_float2(1.f, 0.f);    // low lanes: identity twiddle
        const float p = hi ? -1.f : 1.f;
#pragma unroll
        for (int j = 0; j < 8; j++) {
            float2 o = v[j];
            float2 t;
            t.x = __shfl_xor_sync(0xffffffffu, o.x, m);
            t.y = __shfl_xor_sync(0xffffffffu, o.y, m);
            // low: o + t ; high: (t - o) * tw   -> q = t + p*o (p=+1 low w/ swap ok)
            float2 q = make_float2(t.x + p * o.x, t.y + p * o.y);
            v[j] = cmulf(q, tw);
        }
    }
    // lane L now holds, in slot j: X[j + 8*brev5(L)]
}

__device__ __forceinline__ int brev5(int l) { return (int)(__brev((unsigned)l) >> 27); }

// ---------------------------------------------------------------------------
__global__ void k_tables() {
    int k = threadIdx.x;  // 0..256
    if (k < 256) {
        float a = (2.0f * PI_F) * (float)k / 256.0f;
        g_tw[k] = make_float2(cosf(a), sinf(a));
    }
    if (k < FBINS) {
        float b = PI_F * (float)k / 256.0f;
        g_pk[k] = make_float2(cosf(b), sinf(b));
    }
}

__global__ void k_invwsq(const float* __restrict__ win) {
    int i = blockIdx.x * blockDim.x + threadIdx.x;
    if (i >= OUTLEN) return;
    int tmax = i / HOPSZ;             if (tmax > TVAL - 1) tmax = TVAL - 1;
    int tmin = (i - (NFFT - 1) + HOPSZ - 1) / HOPSZ;  if (tmin < 0) tmin = 0;
    float s = 0.f;
    for (int t = tmin; t <= tmax; t++) {
        int n = i - t * HOPSZ;
        if (n >= 0 && n < NFFT) { float w = win[n]; s += w * w; }
    }
    g_invwsq[i] = (s > 1e-11f) ? (1.0f / s) : 1.0f;
}

__global__ void k_init_ph(const float* __restrict__ ang) {
    int i = blockIdx.x * blockDim.x + threadIdx.x;
    if (i < TOTF) {
        float s, c;
        sincosf(ang[i], &s, &c);
        g_ph[i] = make_float2(c, s);
    }
}

__global__ void k_zero_y() {
    int i = blockIdx.x * blockDim.x + threadIdx.x;
    if (i < (BVAL * OUTLEN) / 4) g_y4[i] = make_float4(0.f, 0.f, 0.f, 0.f);
}

// ---------------------------------------------------------------------------
// ISTFT: spec = mag * phasor -> irfft(512) -> * window -> atomic OLA into g_y
// one frame per warp, 8 warps per block
// ---------------------------------------------------------------------------
__global__ __launch_bounds__(256) void k_istft(const float* __restrict__ mag,
                                               const float* __restrict__ win) {
    __shared__ float2 sw[8][SBUF];
    const int wid = threadIdx.x >> 5;
    const int l   = threadIdx.x & 31;
    const int frame = (blockIdx.x << 3) + wid;
    const int b = frame >> 10;
    const int t = frame & 1023;
    const float*  magp = mag  + (size_t)frame * FBINS;
    const float2* php  = g_ph + (size_t)frame * FBINS;

    float2 v[8];
    // Build packed Z[k] for k = l + 32j directly from gmem (coalesced)
#pragma unroll
    for (int j = 0; j < 8; j++) {
        int k  = l + (j << 5);       // 0..255
        int kr = 256 - k;            // 256..1
        float  mk = magp[k];
        float  mr = magp[kr];
        float2 pk = php[k];
        float2 pr = php[kr];
        float Xkx = mk * pk.x, Xky = mk * pk.y;
        float Xcx = mr * pr.x, Xcy = -mr * pr.y;   // conj(X[256-k])
        if (k == 0) { Xky = 0.f; Xcy = 0.f; }      // irfft ignores imag DC/Nyq
        float Zex = 0.5f * (Xkx + Xcx), Zey = 0.5f * (Xky + Xcy);
        float Bx  = 0.5f * (Xkx - Xcx), By  = 0.5f * (Xky - Xcy);
        float2 e = g_pk[k];                        // e^{+iπk/256}
        float Zox = Bx * e.x - By * e.y;
        float Zoy = Bx * e.y + By * e.x;
        v[j] = make_float2(Zex - Zoy, Zey + Zox);  // Z = Ze + i*Zo
    }
    fft256_warp<1>(v, l);   // inverse, unnormalized

    // undo bit-reversed lane order via warp-private smem
    const int r8 = brev5(l) << 3;
#pragma unroll
    for (int j = 0; j < 8; j++) {
        int n = j + r8;
        sw[wid][IDXP(n)] = v[j];
    }
    __syncwarp();

    float* yb = G_Y + (size_t)b * OUTLEN + t * HOPSZ;
    const float2* w2p = (const float2*)win;
#pragma unroll
    for (int j = 0; j < 8; j++) {
        int m = l + (j << 5);
        float2 z = sw[wid][IDXP(m)];
        float2 w = w2p[m];
        atomicAdd(yb + 2 * m,     z.x * (1.0f / 256.0f) * w.x);
        atomicAdd(yb + 2 * m + 1, z.y * (1.0f / 256.0f) * w.y);
    }
}

// ---------------------------------------------------------------------------
// STFT: gather (reflect-pad + NOLA) -> * window -> rfft(512) -> unit phasor
// ---------------------------------------------------------------------------
__device__ __forceinline__ float sample_at(const float* yb, int i) {
    int j = i - PADN;
    j = (j < 0) ? -j : j;
    if (j >= LTRIM) j = 2 * LTRIM - 2 - j;
    int idx = j + PADN;
    return yb[idx] * g_invwsq[idx];
}

__device__ __forceinline__ float2 norm_phasor(float x, float y) {
    float m2 = x * x + y * y;
    if (m2 < 1e-30f) return make_float2(1.f, 0.f);
    float inv = rsqrtf(m2);
    return make_float2(x * inv, y * inv);
}

__global__ __launch_bounds__(256) void k_stft(const float* __restrict__ win) {
    __shared__ float2 sw[8][SBUF];
    const int wid = threadIdx.x >> 5;
    const int l   = threadIdx.x & 31;
    const int frame = (blockIdx.x << 3) + wid;
    const int b = frame >> 10;
    const int t = frame & 1023;
    const float* yb = G_Y + (size_t)b * OUTLEN;
    const int i0 = t * HOPSZ;

    float2 v[8];
#pragma unroll
    for (int j = 0; j < 8; j++) {
        int m  = l + (j << 5);
        int n0 = 2 * m;
        float x0 = sample_at(yb, i0 + n0);
        float x1 = sample_at(yb, i0 + n0 + 1);
        float2 w = ((const float2*)win)[m];
        v[j] = make_float2(x0 * w.x, x1 * w.y);  // z[m] = x[2m] + i x[2m+1]
    }
    fft256_warp<-1>(v, l);   // forward

    const int r8 = brev5(l) << 3;
#pragma unroll
    for (int j = 0; j < 8; j++) {
        int k = j + r8;
        sw[wid][IDXP(k)] = v[j];
    }
    __syncwarp();

    float2* php = g_ph + (size_t)frame * FBINS;
#pragma unroll
    for (int j = 0; j < 8; j++) {
        int k = l + (j << 5);
        float Xx, Xy;
        if (k == 0) {
            float2 Z0 = sw[wid][IDXP(0)];
            Xx = Z0.x + Z0.y;   // X[0] real
            Xy = 0.f;
        } else {
            float2 Zk = sw[wid][IDXP(k)];
            float2 Zr = sw[wid][IDXP(256 - k)];
            float Zex = 0.5f * (Zk.x + Zr.x);
            float Zey = 0.5f * (Zk.y - Zr.y);
            float dx = Zk.x - Zr.x;
            float dy = Zk.y + Zr.y;
            float Zox = 0.5f * dy;      // Zo = -i/2 * (Zk - conj(Zr))
            float Zoy = -0.5f * dx;
            float2 e = g_pk[k];         // W^k = e^{-iπk/256} = (c, -s)
            float wx = e.x, wy = -e.y;
            Xx = Zex + Zox * wx - Zoy * wy;
            Xy = Zey + Zox * wy + Zoy * wx;
        }
        php[k] = norm_phasor(Xx, Xy);
    }
    if (l == 0) {
        float2 Z0 = sw[wid][IDXP(0)];
        php[256] = norm_phasor(Z0.x - Z0.y, 0.f);   // X[256] real
    }
}

__global__ void k_out(float* __restrict__ out) {
    int i = blockIdx.x * blockDim.x + threadIdx.x;
    if (i < BVAL * LTRIM) {
        int b = i / LTRIM;
        int r = i - b * LTRIM;
        int idx = PADN + r;
        out[i] = G_Y[(size_t)b * OUTLEN + idx] * g_invwsq[idx];
    }
}

// ---------------------------------------------------------------------------
extern "C" void kernel_launch(void* const* d_in, const int* in_sizes, int n_in,
                              void* d_out, int out_size) {
    const float* mag = (const float*)d_in[0];   // [32,1024,257]
    const float* ang = (const float*)d_in[1];   // [32,1024,257]
    const float* win = (const float*)d_in[2];   // [512]
    float* out = (float*)d_out;                 // [32,163680]

    k_tables<<<1, FBINS>>>();
    k_invwsq<<<(OUTLEN + 255) / 256, 256>>>(win);
    k_init_ph<<<TOTF / 256, 256>>>(ang);

    const int zgrid = ((BVAL * OUTLEN) / 4 + 255) / 256;
    const int fgrid = NFRAMES / 8;   // 8 frames (warps) per block
    for (int it = 0; it < NITER; it++) {
        k_zero_y<<<zgrid, 256>>>();
        k_istft<<<fgrid, 256>>>(mag, win);
        k_stft<<<fgrid, 256>>>(win);
    }
    // final ISTFT with converged phases
    k_zero_y<<<zgrid, 256>>>();
    k_istft<<<fgrid, 256>>>(mag, win);
    k_out<<<(BVAL * LTRIM + 255) / 256, 256>>>(out);
}